// round 1
// baseline (speedup 1.0000x reference)
#include <cuda_runtime.h>
#include <stdint.h>

// Problem constants (fixed by the reference: B=64, T=2048, D=64, V=100000)
#define BB 64
#define TT 2048
#define DD 64
#define NROWS (4 * BB)          // 4 features x 64 batches
#define BT (BB * TT)            // 131072

// Output layout (floats), tuple flattened in order:
//   features [B,T,256] @ 0
//   times    [B,T]     @ BT*256
//   delta    [B,T,256] @ BT*256 + BT
//   mask     [B,T,256] @ BT*256 + BT + BT*256
#define OFF_TIMES  (BT * 256)                 // 33554432
#define OFF_DELTA  (OFF_TIMES + BT)           // 33685504
#define OFF_MASK   (OFF_DELTA + BT * 256)     // 67239936

// Scratch for the beta recurrence results: [4][B][T]
__device__ float g_beta[4 * BT];

// ---------------------------------------------------------------------------
// Kernel 1: beta linear-recurrence scan.
// x_t = a_t * x_{t-1} + c_t, with a_t = m_{t-1}*p_t, c_t = dt_t*p_t, x_0 = 0.
// One warp per (feature f, batch b) row; shfl composition scan over 32-chunks.
// ---------------------------------------------------------------------------
__global__ void beta_scan_kernel(const int*   __restrict__ cat1,
                                 const int*   __restrict__ cat2,
                                 const float* __restrict__ num1,
                                 const float* __restrict__ num2,
                                 const float* __restrict__ times)
{
    const int row  = blockIdx.x * (blockDim.x >> 5) + (threadIdx.x >> 5);
    const int lane = threadIdx.x & 31;
    if (row >= NROWS) return;

    const int f = row >> 6;          // 0..3
    const int b = row & 63;          // 0..63
    const float* tr = times + b * TT;

    float carry = 0.0f;

    for (int base = 0; base < TT; base += 32) {
        const int t = base + lane;
        float a, c;
        if (t == 0) {
            a = 0.0f; c = 0.0f;      // beta[0] = 0 (init)
        } else {
            const float tt_cur = tr[t];
            const float dt = tt_cur - tr[t - 1];
            const float p  = (tt_cur != -1.0f) ? 1.0f : 0.0f;
            const int   idx = b * TT + (t - 1);
            float m;
            if (f == 0)      { const int   v = __ldg(cat1 + idx); m = (v != 0 && v != -1) ? 1.0f : 0.0f; }
            else if (f == 1) { const int   v = __ldg(cat2 + idx); m = (v != 0 && v != -1) ? 1.0f : 0.0f; }
            else if (f == 2) { const float v = __ldg(num1 + idx); m = (v != 0.0f && v != -1.0f) ? 1.0f : 0.0f; }
            else             { const float v = __ldg(num2 + idx); m = (v != 0.0f && v != -1.0f) ? 1.0f : 0.0f; }
            a = m * p;
            c = dt * p;
        }

        // Inclusive scan composing (A,C): x_t = A * x_{base-1} + C.
        // combine(self, prev): A = A_self*A_prev; C = C_self + A_self*C_prev.
        #pragma unroll
        for (int off = 1; off < 32; off <<= 1) {
            const float ap = __shfl_up_sync(0xffffffffu, a, off);
            const float cp = __shfl_up_sync(0xffffffffu, c, off);
            if (lane >= off) {
                c = c + a * cp;
                a = a * ap;
            }
        }

        const float beta = c + a * carry;
        g_beta[row * TT + t] = beta;
        carry = __shfl_sync(0xffffffffu, beta, 31);
    }
}

// ---------------------------------------------------------------------------
// Kernel 2: emit all outputs. One warp per (b,t). All stores are float4.
// Features f4 layout (64 float4 per (b,t)):
//   j in [ 0,16): E1[cat1] row f4[j]
//   j in [16,32): E2[cat2] row f4[j-16]
//   j in [32,48): num1*w1+b1 f4[j-32]
//   j in [48,64): num2*w2+b2 f4[j-48]
// ---------------------------------------------------------------------------
__global__ void emit_kernel(const int*   __restrict__ cat1,
                            const int*   __restrict__ cat2,
                            const float* __restrict__ num1,
                            const float* __restrict__ num2,
                            const float* __restrict__ times,
                            const float* __restrict__ E1,
                            const float* __restrict__ E2,
                            const float* __restrict__ w1,
                            const float* __restrict__ b1,
                            const float* __restrict__ w2,
                            const float* __restrict__ b2,
                            float* __restrict__ out)
{
    const int gw   = blockIdx.x * (blockDim.x >> 5) + (threadIdx.x >> 5); // (b,t) index
    const int lane = threadIdx.x & 31;
    if (gw >= BT) return;

    // Per-(b,t) scalars (broadcast via L1)
    const int   c1 = __ldg(cat1 + gw);
    const int   c2 = __ldg(cat2 + gw);
    const float n1 = __ldg(num1 + gw);
    const float n2 = __ldg(num2 + gw);
    const float tm = __ldg(times + gw);

    const float be0 = g_beta[0 * BT + gw];
    const float be1 = g_beta[1 * BT + gw];
    const float be2 = g_beta[2 * BT + gw];
    const float be3 = g_beta[3 * BT + gw];

    const float mk0 = (c1 != 0 && c1 != -1)         ? 1.0f : 0.0f;
    const float mk1 = (c2 != 0 && c2 != -1)         ? 1.0f : 0.0f;
    const float mk2 = (n1 != 0.0f && n1 != -1.0f)   ? 1.0f : 0.0f;
    const float mk3 = (n2 != 0.0f && n2 != -1.0f)   ? 1.0f : 0.0f;

    const float4* e1row = reinterpret_cast<const float4*>(E1 + (size_t)c1 * DD);
    const float4* e2row = reinterpret_cast<const float4*>(E2 + (size_t)c2 * DD);
    const float4* w1v = reinterpret_cast<const float4*>(w1);
    const float4* b1v = reinterpret_cast<const float4*>(b1);
    const float4* w2v = reinterpret_cast<const float4*>(w2);
    const float4* b2v = reinterpret_cast<const float4*>(b2);

    float4* feat4  = reinterpret_cast<float4*>(out) + (size_t)gw * 64;
    float4* delta4 = reinterpret_cast<float4*>(out + OFF_DELTA) + (size_t)gw * 64;
    float4* mask4  = reinterpret_cast<float4*>(out + OFF_MASK)  + (size_t)gw * 64;

    const float betas[4] = {be0, be1, be2, be3};
    const float msks[4]  = {mk0, mk1, mk2, mk3};

    #pragma unroll
    for (int half = 0; half < 2; ++half) {
        const int j = lane + half * 32;
        // features
        float4 v;
        if (j < 16) {
            v = __ldg(e1row + j);
        } else if (j < 32) {
            v = __ldg(e2row + (j - 16));
        } else if (j < 48) {
            const float4 w = __ldg(w1v + (j - 32));
            const float4 o = __ldg(b1v + (j - 32));
            v = make_float4(fmaf(n1, w.x, o.x), fmaf(n1, w.y, o.y),
                            fmaf(n1, w.z, o.z), fmaf(n1, w.w, o.w));
        } else {
            const float4 w = __ldg(w2v + (j - 48));
            const float4 o = __ldg(b2v + (j - 48));
            v = make_float4(fmaf(n2, w.x, o.x), fmaf(n2, w.y, o.y),
                            fmaf(n2, w.z, o.z), fmaf(n2, w.w, o.w));
        }
        feat4[j] = v;

        // delta + mask (broadcast per 16-f4 segment)
        const int fidx = j >> 4;
        const float bv = betas[fidx];
        const float mv = msks[fidx];
        delta4[j] = make_float4(bv, bv, bv, bv);
        mask4[j]  = make_float4(mv, mv, mv, mv);
    }

    if (lane == 0) {
        out[OFF_TIMES + gw] = tm;
    }
}

// ---------------------------------------------------------------------------
// Launch
// Inputs (metadata order): cat1, cat2, num1, num2, event_time, E1, E2,
//                          w1, b1, w2, b2
// ---------------------------------------------------------------------------
extern "C" void kernel_launch(void* const* d_in, const int* in_sizes, int n_in,
                              void* d_out, int out_size)
{
    const int*   cat1  = (const int*)  d_in[0];
    const int*   cat2  = (const int*)  d_in[1];
    const float* num1  = (const float*)d_in[2];
    const float* num2  = (const float*)d_in[3];
    const float* times = (const float*)d_in[4];
    const float* E1    = (const float*)d_in[5];
    const float* E2    = (const float*)d_in[6];
    const float* w1    = (const float*)d_in[7];
    const float* b1    = (const float*)d_in[8];
    const float* w2    = (const float*)d_in[9];
    const float* b2    = (const float*)d_in[10];
    float* out = (float*)d_out;

    // Kernel 1: 256 rows, 8 warps/block -> 32 blocks
    beta_scan_kernel<<<NROWS / 8, 256>>>(cat1, cat2, num1, num2, times);

    // Kernel 2: one warp per (b,t): 131072 warps, 8 warps/block -> 16384 blocks
    emit_kernel<<<BT / 8, 256>>>(cat1, cat2, num1, num2, times,
                                 E1, E2, w1, b1, w2, b2, out);
}

// round 2
// speedup vs baseline: 1.8124x; 1.8124x over previous
#include <cuda_runtime.h>
#include <stdint.h>

// Problem constants (fixed by the reference: B=64, T=2048, D=64, V=100000)
#define BB 64
#define TT 2048
#define DD 64
#define NROWS (4 * BB)          // 4 features x 64 batches
#define BT (BB * TT)            // 131072

// Output layout (floats), tuple flattened in order:
//   features [B,T,256] @ 0
//   times    [B,T]     @ BT*256
//   delta    [B,T,256] @ BT*256 + BT
//   mask     [B,T,256] @ BT*256 + BT + BT*256
#define OFF_TIMES  (BT * 256)                 // 33554432
#define OFF_DELTA  (OFF_TIMES + BT)           // 33685504
#define OFF_MASK   (OFF_DELTA + BT * 256)     // 67239936

// Scratch for the beta recurrence results: [4][B][T]
__device__ float g_beta[4 * BT];

// ---------------------------------------------------------------------------
// Kernel 1: beta linear-recurrence scan, block-per-row two-level scan.
// x_t = a_t * x_{t-1} + c_t, with a_t = m_{t-1}*p_t, c_t = dt_t*p_t, x_0 = 0.
// One 1024-thread block per (feature f, batch b) row; each thread owns 2
// consecutive t. Composition (A,C): x_after = A*x_before + C.
// combine(next, prev): A = A_n*A_p, C = C_n + A_n*C_p.
// ---------------------------------------------------------------------------
__device__ __forceinline__ void load_elem(int f, int t, const float* tr,
                                          const int* c1r, const int* c2r,
                                          const float* n1r, const float* n2r,
                                          float& a, float& c)
{
    if (t == 0) { a = 0.0f; c = 0.0f; return; }
    const float tc = tr[t];
    const float dt = tc - tr[t - 1];
    const float p  = (tc != -1.0f) ? 1.0f : 0.0f;
    float m;
    if (f == 0)      { const int   v = __ldg(c1r + t - 1); m = (v != 0 && v != -1) ? 1.0f : 0.0f; }
    else if (f == 1) { const int   v = __ldg(c2r + t - 1); m = (v != 0 && v != -1) ? 1.0f : 0.0f; }
    else if (f == 2) { const float v = __ldg(n1r + t - 1); m = (v != 0.0f && v != -1.0f) ? 1.0f : 0.0f; }
    else             { const float v = __ldg(n2r + t - 1); m = (v != 0.0f && v != -1.0f) ? 1.0f : 0.0f; }
    a = m * p;
    c = dt * p;
}

__global__ __launch_bounds__(1024) void beta_scan_kernel(
    const int*   __restrict__ cat1,
    const int*   __restrict__ cat2,
    const float* __restrict__ num1,
    const float* __restrict__ num2,
    const float* __restrict__ times)
{
    const int row  = blockIdx.x;        // 0..255
    const int f    = row >> 6;          // 0..3
    const int b    = row & 63;          // 0..63
    const int tid  = threadIdx.x;       // 0..1023
    const int lane = tid & 31;
    const int wid  = tid >> 5;          // 0..31

    __shared__ float sA[32], sC[32];

    const float* tr  = times + b * TT;
    const int*   c1r = cat1  + b * TT;
    const int*   c2r = cat2  + b * TT;
    const float* n1r = num1  + b * TT;
    const float* n2r = num2  + b * TT;

    const int t0 = tid * 2;
    float a0, c0, a1, c1;
    load_elem(f, t0,     tr, c1r, c2r, n1r, n2r, a0, c0);
    load_elem(f, t0 + 1, tr, c1r, c2r, n1r, n2r, a1, c1);

    // Pair composition (apply t0 then t1)
    float A = a1 * a0;
    float C = c1 + a1 * c0;

    // Warp inclusive scan of pair-compositions
    #pragma unroll
    for (int off = 1; off < 32; off <<= 1) {
        const float Ap = __shfl_up_sync(0xffffffffu, A, off);
        const float Cp = __shfl_up_sync(0xffffffffu, C, off);
        if (lane >= off) {
            C = C + A * Cp;
            A = A * Ap;
        }
    }

    // Warp aggregate -> smem
    if (lane == 31) { sA[wid] = A; sC[wid] = C; }
    __syncthreads();

    // Warp 0 scans the 32 warp aggregates, writes back EXCLUSIVE prefixes
    if (wid == 0) {
        float Aw = sA[lane], Cw = sC[lane];
        #pragma unroll
        for (int off = 1; off < 32; off <<= 1) {
            const float Ap = __shfl_up_sync(0xffffffffu, Aw, off);
            const float Cp = __shfl_up_sync(0xffffffffu, Cw, off);
            if (lane >= off) {
                Cw = Cw + Aw * Cp;
                Aw = Aw * Ap;
            }
        }
        float Ae = __shfl_up_sync(0xffffffffu, Aw, 1);
        float Ce = __shfl_up_sync(0xffffffffu, Cw, 1);
        if (lane == 0) { Ae = 1.0f; Ce = 0.0f; }
        sA[lane] = Ae; sC[lane] = Ce;
    }
    __syncthreads();

    // Thread-exclusive within warp
    float Ax = __shfl_up_sync(0xffffffffu, A, 1);
    float Cx = __shfl_up_sync(0xffffffffu, C, 1);
    if (lane == 0) { Ax = 1.0f; Cx = 0.0f; }

    // Total exclusive prefix for this thread: warp prefix then thread prefix.
    // x starts at 0 => x_pre = Cx + Ax * Cw_excl  (A terms multiply 0)
    const float Cw = sC[wid];
    const float xpre = Cx + Ax * Cw;

    const float x0v = c0 + a0 * xpre;
    const float x1v = c1 + a1 * x0v;

    float* br = g_beta + (size_t)row * TT;
    br[t0]     = x0v;
    br[t0 + 1] = x1v;
}

// ---------------------------------------------------------------------------
// Kernel 2: emit all outputs. One warp per (b,t). All stores are float4 with
// streaming (evict-first) hint so output writes don't evict E1/E2 from L2.
// ---------------------------------------------------------------------------
__global__ void emit_kernel(const int*   __restrict__ cat1,
                            const int*   __restrict__ cat2,
                            const float* __restrict__ num1,
                            const float* __restrict__ num2,
                            const float* __restrict__ times,
                            const float* __restrict__ E1,
                            const float* __restrict__ E2,
                            const float* __restrict__ w1,
                            const float* __restrict__ b1,
                            const float* __restrict__ w2,
                            const float* __restrict__ b2,
                            float* __restrict__ out)
{
    const int gw   = blockIdx.x * (blockDim.x >> 5) + (threadIdx.x >> 5); // (b,t)
    const int lane = threadIdx.x & 31;
    if (gw >= BT) return;

    const int   c1 = __ldg(cat1 + gw);
    const int   c2 = __ldg(cat2 + gw);
    const float n1 = __ldg(num1 + gw);
    const float n2 = __ldg(num2 + gw);
    const float tm = __ldg(times + gw);

    const float be0 = g_beta[0 * BT + gw];
    const float be1 = g_beta[1 * BT + gw];
    const float be2 = g_beta[2 * BT + gw];
    const float be3 = g_beta[3 * BT + gw];

    const float mk0 = (c1 != 0 && c1 != -1)       ? 1.0f : 0.0f;
    const float mk1 = (c2 != 0 && c2 != -1)       ? 1.0f : 0.0f;
    const float mk2 = (n1 != 0.0f && n1 != -1.0f) ? 1.0f : 0.0f;
    const float mk3 = (n2 != 0.0f && n2 != -1.0f) ? 1.0f : 0.0f;

    const float4* e1row = reinterpret_cast<const float4*>(E1 + (size_t)c1 * DD);
    const float4* e2row = reinterpret_cast<const float4*>(E2 + (size_t)c2 * DD);
    const float4* w1v = reinterpret_cast<const float4*>(w1);
    const float4* b1v = reinterpret_cast<const float4*>(b1);
    const float4* w2v = reinterpret_cast<const float4*>(w2);
    const float4* b2v = reinterpret_cast<const float4*>(b2);

    float4* feat4  = reinterpret_cast<float4*>(out) + (size_t)gw * 64;
    float4* delta4 = reinterpret_cast<float4*>(out + OFF_DELTA) + (size_t)gw * 64;
    float4* mask4  = reinterpret_cast<float4*>(out + OFF_MASK)  + (size_t)gw * 64;

    const float betas[4] = {be0, be1, be2, be3};
    const float msks[4]  = {mk0, mk1, mk2, mk3};

    #pragma unroll
    for (int half = 0; half < 2; ++half) {
        const int j = lane + half * 32;
        float4 v;
        if (j < 16) {
            v = __ldg(e1row + j);
        } else if (j < 32) {
            v = __ldg(e2row + (j - 16));
        } else if (j < 48) {
            const float4 w = __ldg(w1v + (j - 32));
            const float4 o = __ldg(b1v + (j - 32));
            v = make_float4(fmaf(n1, w.x, o.x), fmaf(n1, w.y, o.y),
                            fmaf(n1, w.z, o.z), fmaf(n1, w.w, o.w));
        } else {
            const float4 w = __ldg(w2v + (j - 48));
            const float4 o = __ldg(b2v + (j - 48));
            v = make_float4(fmaf(n2, w.x, o.x), fmaf(n2, w.y, o.y),
                            fmaf(n2, w.z, o.z), fmaf(n2, w.w, o.w));
        }
        __stcs(feat4 + j, v);

        const int fidx = j >> 4;
        const float bv = betas[fidx];
        const float mv = msks[fidx];
        __stcs(delta4 + j, make_float4(bv, bv, bv, bv));
        __stcs(mask4  + j, make_float4(mv, mv, mv, mv));
    }

    if (lane == 0) {
        __stcs(out + OFF_TIMES + gw, tm);
    }
}

// ---------------------------------------------------------------------------
// Launch
// Inputs (metadata order): cat1, cat2, num1, num2, event_time, E1, E2,
//                          w1, b1, w2, b2
// ---------------------------------------------------------------------------
extern "C" void kernel_launch(void* const* d_in, const int* in_sizes, int n_in,
                              void* d_out, int out_size)
{
    const int*   cat1  = (const int*)  d_in[0];
    const int*   cat2  = (const int*)  d_in[1];
    const float* num1  = (const float*)d_in[2];
    const float* num2  = (const float*)d_in[3];
    const float* times = (const float*)d_in[4];
    const float* E1    = (const float*)d_in[5];
    const float* E2    = (const float*)d_in[6];
    const float* w1    = (const float*)d_in[7];
    const float* b1    = (const float*)d_in[8];
    const float* w2    = (const float*)d_in[9];
    const float* b2    = (const float*)d_in[10];
    float* out = (float*)d_out;

    // Kernel 1: one 1024-thread block per (f,b) row
    beta_scan_kernel<<<NROWS, 1024>>>(cat1, cat2, num1, num2, times);

    // Kernel 2: one warp per (b,t): 131072 warps, 8 warps/block
    emit_kernel<<<BT / 8, 256>>>(cat1, cat2, num1, num2, times,
                                 E1, E2, w1, b1, w2, b2, out);
}